// round 5
// baseline (speedup 1.0000x reference)
#include <cuda_runtime.h>
#include <cstdint>

#define N_NODES 8192
#define N_EDGES 24576
#define D_FEAT  64
#define N_QUBITS 16
#define PI_F 3.14159265358979f

#define SCAN_BLOCKS 2368            // 148 * 16
#define SCAN_THREADS 256
#define NODE_BLOCKS (N_NODES / 8)   // blocks 0..1023 run node prologue
#define EDGE_BLOCKS 96              // blocks 0..95 run edge phase after bar1

// Scratch (no device mallocs allowed)
__device__ int      g_idx_o[N_EDGES];
__device__ int      g_idx_i[N_EDGES];
__device__ float    g_H[N_NODES * 32]; // [n][0:16]=X[n]@W_top, [n][16:32]=X[n]@W_bot
__device__ unsigned g_min_bits;
__device__ unsigned g_max_bits;
__device__ unsigned g_cnt1 = 0;  // bar1: all SCAN_BLOCKS; reset by last through bar2
__device__ unsigned g_cnt2 = 0;  // bar2: EDGE_BLOCKS;   reset by block 0 next replay

// ---------------------------------------------------------------------------
// One fused persistent kernel:
//  Phase A: node precompute (blocks < NODE_BLOCKS) + streaming scan (all).
//  bar1:    all blocks release-arrive; only edge blocks spin (others exit,
//           freeing SM slots -> no starvation/deadlock even across waves).
//  Phase B: edge blocks: h = relu(Hs[src]+Ht[tgt]+b), block min/max -> atomics.
//  bar2:    edge blocks; last arriver resets g_cnt1 for the next replay.
//  Phase C: read global lo/hi, normalize in-register, coalesced store.
// Counter/scalar resets are placed so every graph replay sees fresh state.
// ---------------------------------------------------------------------------
__global__ void __launch_bounds__(SCAN_THREADS)
fused_kernel(const uint4* __restrict__ Mo,
             const uint4* __restrict__ Mi,
             const float* __restrict__ X,
             const float* __restrict__ W,
             const float* __restrict__ b,
             float* __restrict__ out) {
    const int tid = threadIdx.x;

    // per-replay reset (ordered before all uses via the bar1 release chain)
    if (blockIdx.x == 0 && tid == 0) {
        g_min_bits = 0x7F800000u;   // +inf
        g_max_bits = 0x00000000u;   // relu outputs >= 0
        g_cnt2     = 0u;
    }

    // ---- Phase A1: node prologue (8 nodes per block, warp per node) ----
    __shared__ float sW[2 * D_FEAT * N_QUBITS];   // 8 KB
    __shared__ float sX[8][D_FEAT];               // 2 KB
    if (blockIdx.x < NODE_BLOCKS) {
        const int wid  = tid >> 5;
        const int lane = tid & 31;

        const float4* W4 = (const float4*)W;
        ((float4*)sW)[tid]       = W4[tid];
        ((float4*)sW)[tid + 256] = W4[tid + 256];

        const int n = blockIdx.x * 8 + wid;
        ((float2*)sX[wid])[lane] = ((const float2*)(X + (long)n * D_FEAT))[lane];
        __syncthreads();

        const int q    = lane & 15;
        const int half = lane >> 4;   // 0 = W[0:64], 1 = W[64:128]
        const float* w = sW + half * D_FEAT * N_QUBITS + q;
        const float* x = sX[wid];

        float acc = 0.0f;
#pragma unroll
        for (int d = 0; d < D_FEAT; d++)
            acc = fmaf(x[d], w[d * N_QUBITS], acc);

        g_H[(long)n * 32 + lane] = acc;   // coalesced 128B per warp
    }

    // ---- Phase A2: streaming scan of both one-hot incidence matrices ----
    // Nonzero (==1.0f) at linear pos p of [N_NODES, N_EDGES] row-major
    // => idx[p % E] = p / E. Integer OR test (values are 0 or 0x3F800000).
    {
        const long total4 = (long)N_NODES * N_EDGES / 4;
        const long stride = (long)SCAN_BLOCKS * SCAN_THREADS;
        long i = (long)blockIdx.x * SCAN_THREADS + tid;

#define PROCESS(v, I, IDX)                                              \
        if (((v).x | (v).y | (v).z | (v).w) != 0u) {                    \
            long base = (I) * 4;                                        \
            int n = (int)(base / N_EDGES);                              \
            int e = (int)(base % N_EDGES);                              \
            if ((v).x != 0u) IDX[e + 0] = n;                            \
            if ((v).y != 0u) IDX[e + 1] = n;                            \
            if ((v).z != 0u) IDX[e + 2] = n;                            \
            if ((v).w != 0u) IDX[e + 3] = n;                            \
        }

        for (; i + stride < total4; i += 2 * stride) {
            uint4 a0 = Mo[i];
            uint4 a1 = Mo[i + stride];
            uint4 b0 = Mi[i];
            uint4 b1 = Mi[i + stride];
            PROCESS(a0, i,          g_idx_o)
            PROCESS(a1, i + stride, g_idx_o)
            PROCESS(b0, i,          g_idx_i)
            PROCESS(b1, i + stride, g_idx_i)
        }
        for (; i < total4; i += stride) {
            uint4 a = Mo[i];
            uint4 bv = Mi[i];
            PROCESS(a,  i, g_idx_o)
            PROCESS(bv, i, g_idx_i)
        }
#undef PROCESS
    }

    // ---- bar1 ----
    const bool edge_block = (blockIdx.x < EDGE_BLOCKS);
    __syncthreads();                 // all block stores happen-before tid0 ops
    if (tid == 0) {
        __threadfence();             // publish this block's idx/H stores
        atomicAdd(&g_cnt1, 1u);
        if (edge_block) {
            while (atomicAdd(&g_cnt1, 0u) < SCAN_BLOCKS) __nanosleep(32);
            __threadfence();         // acquire
        }
    }
    if (!edge_block) return;
    __syncthreads();                 // edge blocks: wait for tid0's spin

    // ---- Phase B: edge compute (one thread per edge) ----
    __shared__ float s_min[8], s_max[8];
    __shared__ float s_lo, s_hi;

    const int e   = blockIdx.x * 256 + tid;
    const int src = g_idx_o[e];
    const int tgt = g_idx_i[e];

    const float4* hs = (const float4*)(g_H + (long)src * 32);
    const float4* ht = (const float4*)(g_H + (long)tgt * 32 + 16);
    const float4* b4 = (const float4*)b;

    float4 h[4];
    float tmin = 3.4e38f, tmax = 0.0f;
#pragma unroll
    for (int k = 0; k < 4; k++) {
        float4 a = hs[k];
        float4 c = ht[k];
        float4 bb = b4[k];
        h[k].x = fmaxf(a.x + c.x + bb.x, 0.0f);
        h[k].y = fmaxf(a.y + c.y + bb.y, 0.0f);
        h[k].z = fmaxf(a.z + c.z + bb.z, 0.0f);
        h[k].w = fmaxf(a.w + c.w + bb.w, 0.0f);
        tmin = fminf(tmin, fminf(fminf(h[k].x, h[k].y), fminf(h[k].z, h[k].w)));
        tmax = fmaxf(tmax, fmaxf(fmaxf(h[k].x, h[k].y), fmaxf(h[k].z, h[k].w)));
    }

#pragma unroll
    for (int off = 16; off > 0; off >>= 1) {
        tmin = fminf(tmin, __shfl_xor_sync(0xFFFFFFFF, tmin, off));
        tmax = fmaxf(tmax, __shfl_xor_sync(0xFFFFFFFF, tmax, off));
    }
    const int wid = tid >> 5, lid = tid & 31;
    if (lid == 0) { s_min[wid] = tmin; s_max[wid] = tmax; }
    __syncthreads();

    // ---- bar2 + global min/max resolve ----
    if (tid == 0) {
        float bmin = s_min[0], bmax = s_max[0];
#pragma unroll
        for (int w = 1; w < 8; w++) {
            bmin = fminf(bmin, s_min[w]);
            bmax = fmaxf(bmax, s_max[w]);
        }
        // nonneg floats: uint bit pattern preserves ordering
        atomicMin(&g_min_bits, __float_as_uint(bmin));
        atomicMax(&g_max_bits, __float_as_uint(bmax));
        __threadfence();
        unsigned old = atomicAdd(&g_cnt2, 1u);
        if (old == EDGE_BLOCKS - 1)
            atomicExch(&g_cnt1, 0u);   // all blocks provably past bar1
        while (atomicAdd(&g_cnt2, 0u) < EDGE_BLOCKS) __nanosleep(32);
        s_lo = __uint_as_float(atomicAdd(&g_min_bits, 0u));
        s_hi = __uint_as_float(atomicAdd(&g_max_bits, 0u));
    }
    __syncthreads();

    // ---- Phase C: normalize + coalesced store ----
    const float lo = s_lo;
    const float s  = PI_F / (s_hi - lo);

    float4* o4 = (float4*)(out + (long)e * N_QUBITS);
#pragma unroll
    for (int k = 0; k < 4; k++) {
        o4[k] = make_float4((h[k].x - lo) * s, (h[k].y - lo) * s,
                            (h[k].z - lo) * s, (h[k].w - lo) * s);
    }
}

extern "C" void kernel_launch(void* const* d_in, const int* in_sizes, int n_in,
                              void* d_out, int out_size) {
    const float* X    = (const float*)d_in[0];   // [8192, 64]
    const float* Ri   = (const float*)d_in[1];   // [8192, 24576]
    const float* Ro   = (const float*)d_in[2];   // [8192, 24576]
    const float* W_in = (const float*)d_in[3];   // [128, 16]
    const float* b_in = (const float*)d_in[4];   // [16]
    float* out = (float*)d_out;                  // [24576, 16]

    fused_kernel<<<SCAN_BLOCKS, SCAN_THREADS>>>((const uint4*)Ro, (const uint4*)Ri,
                                                X, W_in, b_in, out);
}

// round 6
// speedup vs baseline: 1.0665x; 1.0665x over previous
#include <cuda_runtime.h>
#include <cstdint>

#define N_NODES 8192
#define N_EDGES 24576
#define D_FEAT  64
#define N_QUBITS 16
#define PI_F 3.14159265358979f

#define SCAN_BLOCKS (148 * 16)
#define SCAN_THREADS 256
#define NODE_BLOCKS (N_NODES / 8)        // blocks 0..1023 run node prologue

// Scratch (no device mallocs allowed)
__device__ int      g_idx_o[N_EDGES];
__device__ int      g_idx_i[N_EDGES];
__device__ float    g_H[N_NODES * 32];   // [n][0:16]=X[n]@W_top, [n][16:32]=X[n]@W_bot
__device__ unsigned g_min_bits;
__device__ unsigned g_max_bits;
__device__ unsigned g_arrive;

// ---------------------------------------------------------------------------
// Fused: (a) node precompute prologue on blocks < NODE_BLOCKS,
//        (b) streaming scan of both one-hot incidence matrices.
// Streaming loads use __ldcs (evict-first) — data is single-use, keep it out
// of L2's working set. All hot-loop indexing is 32-bit (total4 < 2^31).
// Nonzero (==1.0f, bits 0x3F800000) at linear pos p of [N_NODES, N_EDGES]
// row-major means idx[p % E] = p / E.
// ---------------------------------------------------------------------------
__global__ void __launch_bounds__(SCAN_THREADS)
scan_kernel(const uint4* __restrict__ Mo,
            const uint4* __restrict__ Mi,
            const float* __restrict__ X,
            const float* __restrict__ W) {
    const int tid = threadIdx.x;

    if (blockIdx.x == 0 && tid == 0) {
        g_min_bits = 0x7F800000u;   // +inf
        g_max_bits = 0x00000000u;   // relu outputs >= 0
        g_arrive   = 0u;
    }

    // ---- node prologue: Hs[n][q], Ht[n][q] for 8 nodes per block ----
    if (blockIdx.x < NODE_BLOCKS) {
        __shared__ float sW[2 * D_FEAT * N_QUBITS];   // 8 KB
        __shared__ float sX[8][D_FEAT];

        const int wid  = tid >> 5;
        const int lane = tid & 31;

        const float4* W4 = (const float4*)W;
        ((float4*)sW)[tid]       = W4[tid];
        ((float4*)sW)[tid + 256] = W4[tid + 256];

        const int n = blockIdx.x * 8 + wid;
        ((float2*)sX[wid])[lane] = ((const float2*)(X + (long)n * D_FEAT))[lane];
        __syncthreads();

        const int q    = lane & 15;
        const int half = lane >> 4;   // 0 = W[0:64], 1 = W[64:128]
        const float* w = sW + half * D_FEAT * N_QUBITS + q;
        const float* x = sX[wid];

        float acc = 0.0f;
#pragma unroll
        for (int d = 0; d < D_FEAT; d++)
            acc = fmaf(x[d], w[d * N_QUBITS], acc);

        g_H[(long)n * 32 + lane] = acc;   // coalesced 128B per warp
    }

    // ---- streaming scan (32-bit indices; evict-first loads) ----
    const unsigned total4 = (unsigned)(N_NODES / 4) * N_EDGES;  // 50,331,648
    const unsigned stride = SCAN_BLOCKS * SCAN_THREADS;
    unsigned i = blockIdx.x * SCAN_THREADS + tid;

#define PROCESS(v, I, IDX)                                              \
    if (((v).x | (v).y | (v).z | (v).w) != 0u) {                        \
        unsigned base = (I) * 4u;                                       \
        unsigned n = base / N_EDGES;                                    \
        unsigned e = base % N_EDGES;                                    \
        if ((v).x != 0u) IDX[e + 0] = n;                                \
        if ((v).y != 0u) IDX[e + 1] = n;                                \
        if ((v).z != 0u) IDX[e + 2] = n;                                \
        if ((v).w != 0u) IDX[e + 3] = n;                                \
    }

    for (; i + stride < total4; i += 2 * stride) {
        uint4 a0 = __ldcs(&Mo[i]);
        uint4 a1 = __ldcs(&Mo[i + stride]);
        uint4 b0 = __ldcs(&Mi[i]);
        uint4 b1 = __ldcs(&Mi[i + stride]);
        PROCESS(a0, i,          g_idx_o)
        PROCESS(a1, i + stride, g_idx_o)
        PROCESS(b0, i,          g_idx_i)
        PROCESS(b1, i + stride, g_idx_i)
    }
    for (; i < total4; i += stride) {
        uint4 a = __ldcs(&Mo[i]);
        uint4 b = __ldcs(&Mi[i]);
        PROCESS(a, i, g_idx_o)
        PROCESS(b, i, g_idx_i)
    }
#undef PROCESS
}

// ---------------------------------------------------------------------------
// Edge stage: h[e] = relu(Hs[src[e]] + Ht[tgt[e]] + b); global min/max via
// atomics + single-wave grid barrier (96 blocks); normalize in-register;
// single coalesced store. One thread per edge.
// ---------------------------------------------------------------------------
__global__ void __launch_bounds__(256, 3)
edge_kernel(const float* __restrict__ b,
            float* __restrict__ out) {
    __shared__ float s_min[8], s_max[8];
    __shared__ float s_lo, s_hi;

    const int tid = threadIdx.x;
    const int e   = blockIdx.x * 256 + tid;

    const int src = g_idx_o[e];
    const int tgt = g_idx_i[e];

    const float4* hs = (const float4*)(g_H + (long)src * 32);
    const float4* ht = (const float4*)(g_H + (long)tgt * 32 + 16);
    const float4* b4 = (const float4*)b;

    float4 h[4];
    float tmin = 3.4e38f, tmax = 0.0f;
#pragma unroll
    for (int k = 0; k < 4; k++) {
        float4 a = hs[k];
        float4 c = ht[k];
        float4 bb = b4[k];
        h[k].x = fmaxf(a.x + c.x + bb.x, 0.0f);
        h[k].y = fmaxf(a.y + c.y + bb.y, 0.0f);
        h[k].z = fmaxf(a.z + c.z + bb.z, 0.0f);
        h[k].w = fmaxf(a.w + c.w + bb.w, 0.0f);
        tmin = fminf(tmin, fminf(fminf(h[k].x, h[k].y), fminf(h[k].z, h[k].w)));
        tmax = fmaxf(tmax, fmaxf(fmaxf(h[k].x, h[k].y), fmaxf(h[k].z, h[k].w)));
    }

#pragma unroll
    for (int off = 16; off > 0; off >>= 1) {
        tmin = fminf(tmin, __shfl_xor_sync(0xFFFFFFFF, tmin, off));
        tmax = fmaxf(tmax, __shfl_xor_sync(0xFFFFFFFF, tmax, off));
    }
    int wid = tid >> 5, lid = tid & 31;
    if (lid == 0) { s_min[wid] = tmin; s_max[wid] = tmax; }
    __syncthreads();

    if (tid == 0) {
        float bmin = s_min[0], bmax = s_max[0];
#pragma unroll
        for (int w = 1; w < 8; w++) {
            bmin = fminf(bmin, s_min[w]);
            bmax = fmaxf(bmax, s_max[w]);
        }
        // nonneg floats: uint bit pattern preserves ordering
        atomicMin(&g_min_bits, __float_as_uint(bmin));
        atomicMax(&g_max_bits, __float_as_uint(bmax));
        __threadfence();
        atomicAdd(&g_arrive, 1u);
        // single-wave grid barrier (96 blocks << 148*3 resident slots)
        while (atomicAdd(&g_arrive, 0u) < gridDim.x) __nanosleep(32);
        s_lo = __uint_as_float(atomicAdd(&g_min_bits, 0u));
        s_hi = __uint_as_float(atomicAdd(&g_max_bits, 0u));
    }
    __syncthreads();

    const float lo = s_lo;
    const float s  = PI_F / (s_hi - lo);

    float4* o4 = (float4*)(out + (long)e * N_QUBITS);
#pragma unroll
    for (int k = 0; k < 4; k++) {
        o4[k] = make_float4((h[k].x - lo) * s, (h[k].y - lo) * s,
                            (h[k].z - lo) * s, (h[k].w - lo) * s);
    }
}

extern "C" void kernel_launch(void* const* d_in, const int* in_sizes, int n_in,
                              void* d_out, int out_size) {
    const float* X    = (const float*)d_in[0];   // [8192, 64]
    const float* Ri   = (const float*)d_in[1];   // [8192, 24576]
    const float* Ro   = (const float*)d_in[2];   // [8192, 24576]
    const float* W_in = (const float*)d_in[3];   // [128, 16]
    const float* b_in = (const float*)d_in[4];   // [16]
    float* out = (float*)d_out;                  // [24576, 16]

    scan_kernel<<<SCAN_BLOCKS, SCAN_THREADS>>>((const uint4*)Ro, (const uint4*)Ri,
                                               X, W_in);

    edge_kernel<<<N_EDGES / 256, 256>>>(b_in, out);
}